// round 1
// baseline (speedup 1.0000x reference)
#include <cuda_runtime.h>
#include <math.h>

#define EPSV 1e-5f

// ---------------- scratch (static device globals; no allocs) ----------------
__device__ float g_h1[4 * 64 * 64 * 128];    // conv1 out, NHWC
__device__ float g_col[16384 * 1152];        // im2col scratch (reused)
__device__ float g_h2[16384 * 256];          // conv2 out, NHWC (rows = b*4096 + y*64 + x)
__device__ float g_s[4096 * 256];            // sequence [b*l, dm]
__device__ float g_xr[4096 * 1024];          // in_proj out (xi | res)
__device__ float g_xl[4096 * 512];           // after depthwise conv
__device__ float g_xdbl[4096 * 64];          // x_proj out (dt|B|C)
__device__ float g_delta[4096 * 512];
__device__ float g_y[4096 * 512];            // scan out * silu(res)
__device__ float g_tmp[4096 * 256];          // out_proj out
__device__ float g_v[4 * 256];               // pooled+LN features

__device__ __forceinline__ float gelu_f(float v) {
    return 0.5f * v * (1.f + erff(v * 0.70710678118654752440f));
}
__device__ __forceinline__ float softplus_f(float x) {
    return fmaxf(x, 0.f) + log1pf(expf(-fabsf(x)));
}

// ---------------- generic SGEMM: C[M,N] = A[M,K] * B[N,K]^T ----------------
// EPI: 0=none, 1=+bias, 2=gelu((acc+bias)*g/sqrt(1+eps)+beta), 3=softplus(acc+bias)
#define BM 128
#define BN 128
#define BKK 8
template <int EPI>
__global__ void sgemm_nt(const float* __restrict__ A, int lda,
                         const float* __restrict__ B, int ldb,
                         float* __restrict__ C, int ldc,
                         int M, int N, int K,
                         const float* __restrict__ bias,
                         const float* __restrict__ bn_g,
                         const float* __restrict__ bn_b) {
    __shared__ float As[BKK][BM];
    __shared__ float Bs[BKK][BN];
    const int tid = threadIdx.x;           // 256 threads
    const int rowBase = blockIdx.y * BM;
    const int colBase = blockIdx.x * BN;
    const int aRow = tid >> 1;
    const int aCol = (tid & 1) * 4;
    const int tx = tid & 15, ty = tid >> 4;

    float acc[8][8];
#pragma unroll
    for (int i = 0; i < 8; i++)
#pragma unroll
        for (int j = 0; j < 8; j++) acc[i][j] = 0.f;

    for (int k0 = 0; k0 < K; k0 += BKK) {
#pragma unroll
        for (int i = 0; i < 4; i++) {
            int gr = rowBase + aRow, gk = k0 + aCol + i;
            As[aCol + i][aRow] = (gr < M && gk < K) ? A[(size_t)gr * lda + gk] : 0.f;
        }
#pragma unroll
        for (int i = 0; i < 4; i++) {
            int gn = colBase + aRow, gk = k0 + aCol + i;
            Bs[aCol + i][aRow] = (gn < N && gk < K) ? B[(size_t)gn * ldb + gk] : 0.f;
        }
        __syncthreads();
#pragma unroll
        for (int kk = 0; kk < BKK; kk++) {
            float ar[8], br[8];
#pragma unroll
            for (int i = 0; i < 8; i++) ar[i] = As[kk][ty * 8 + i];
#pragma unroll
            for (int j = 0; j < 8; j++) br[j] = Bs[kk][tx * 8 + j];
#pragma unroll
            for (int i = 0; i < 8; i++)
#pragma unroll
                for (int j = 0; j < 8; j++) acc[i][j] += ar[i] * br[j];
        }
        __syncthreads();
    }
#pragma unroll
    for (int i = 0; i < 8; i++) {
        int r = rowBase + ty * 8 + i;
        if (r >= M) continue;
#pragma unroll
        for (int j = 0; j < 8; j++) {
            int c = colBase + tx * 8 + j;
            if (c >= N) continue;
            float v = acc[i][j];
            if (EPI == 1) v += bias[c];
            else if (EPI == 2) {
                v += bias[c];
                v = v * (bn_g[c] * rsqrtf(1.f + EPSV)) + bn_b[c];
                v = gelu_f(v);
            } else if (EPI == 3) {
                v = softplus_f(v + bias[c]);
            }
            C[(size_t)r * ldc + c] = v;
        }
    }
}

// ---------------- conv stem ----------------
__global__ void conv1_kernel(const float* __restrict__ x, const float* __restrict__ w,
                             const float* __restrict__ bias, const float* __restrict__ g,
                             const float* __restrict__ bb) {
    int idx = blockIdx.x * 256 + threadIdx.x;
    if (idx >= 4 * 64 * 64 * 128) return;
    int co = idx & 127;
    int xx = (idx >> 7) & 63;
    int yy = (idx >> 13) & 63;
    int b = idx >> 19;
    float acc = bias[co];
#pragma unroll
    for (int ci = 0; ci < 3; ci++)
#pragma unroll
        for (int ky = 0; ky < 3; ky++) {
            int iy = yy + ky - 1;
            if ((unsigned)iy >= 64u) continue;
#pragma unroll
            for (int kx = 0; kx < 3; kx++) {
                int ix = xx + kx - 1;
                if ((unsigned)ix >= 64u) continue;
                acc += x[((b * 3 + ci) * 64 + iy) * 64 + ix] * w[((co * 3 + ci) * 3 + ky) * 3 + kx];
            }
        }
    float v = acc * (g[co] * rsqrtf(1.f + EPSV)) + bb[co];
    g_h1[idx] = gelu_f(v);
}

__global__ void im2col1_kernel() {
    int idx = blockIdx.x * 256 + threadIdx.x;
    if (idx >= 16384 * 1152) return;
    int k = idx % 1152;
    int row = idx / 1152;
    int ci = k / 9, r = k % 9;
    int ky = r / 3, kx = r % 3;
    int xx = row & 63, yy = (row >> 6) & 63, b = row >> 12;
    int iy = yy + ky - 1, ix = xx + kx - 1;
    float v = 0.f;
    if ((unsigned)iy < 64u && (unsigned)ix < 64u)
        v = g_h1[(((b * 64 + iy) * 64 + ix) << 7) + ci];
    g_col[idx] = v;
}

__global__ void im2col2_kernel() {
    int idx = blockIdx.x * 256 + threadIdx.x;
    if (idx >= 4096 * 1024) return;
    int k = idx & 1023;
    int row = idx >> 10;
    int ci = k >> 2, r = k & 3, ky = r >> 1, kx = r & 1;
    int ox = row & 31, oy = (row >> 5) & 31, b = row >> 10;
    g_col[idx] = g_h2[(((b * 64 + 2 * oy + ky) * 64 + 2 * ox + kx) << 8) + ci];
}

// ---------------- mamba pieces ----------------
__global__ void dwconv_kernel(const float* __restrict__ cw, const float* __restrict__ cb) {
    int idx = blockIdx.x * 256 + threadIdx.x;
    if (idx >= 4096 * 512) return;
    int d = idx & 511;
    int row = idx >> 9;
    int l = row & 1023, b = row >> 10;
    float acc = cb[d];
#pragma unroll
    for (int k = 0; k < 4; k++) {
        int ll = l + k - 1;
        if ((unsigned)ll < 1024u)
            acc += g_xr[((size_t)(b * 1024 + ll) << 10) + d] * cw[d * 4 + k];
    }
    g_xl[idx] = acc;
}

// 16 lanes per (b,d) chain, one lane per state n. Fuses +u*D and *silu(res).
__global__ void scan_kernel(const float* __restrict__ alog_l, const float* __restrict__ dssm_l) {
    int gid = blockIdx.x * 256 + threadIdx.x;
    int n = gid & 15;
    int grp = gid >> 4;     // (b,d)
    int d = grp & 511;
    int b = grp >> 9;
    float Adn = -expf(alog_l[d * 16 + n]);
    float Dd = dssm_l[d];
    float h = 0.f;
    for (int l = 0; l < 1024; l++) {
        int row = b * 1024 + l;
        float dl = g_delta[((size_t)row << 9) + d];
        float u = g_xl[((size_t)row << 9) + d];
        float Bv = g_xdbl[(row << 6) + 32 + n];
        float Cv = g_xdbl[(row << 6) + 48 + n];
        float a = expf(dl * Adn);
        h = a * h + dl * Bv * u;
        float p = h * Cv;
        p += __shfl_xor_sync(0xFFFFFFFFu, p, 1);
        p += __shfl_xor_sync(0xFFFFFFFFu, p, 2);
        p += __shfl_xor_sync(0xFFFFFFFFu, p, 4);
        p += __shfl_xor_sync(0xFFFFFFFFu, p, 8);
        if (n == 0) {
            float rr = g_xr[((size_t)row << 10) + 512 + d];
            float sil = rr / (1.f + expf(-rr));
            g_y[((size_t)row << 9) + d] = (p + u * Dd) * sil;
        }
    }
}

__global__ void ln_add_kernel(const float* __restrict__ w, const float* __restrict__ bi) {
    int row = blockIdx.x;
    int t = threadIdx.x;
    __shared__ float sh[256];
    float v = g_tmp[(size_t)row * 256 + t];
    sh[t] = v;
    __syncthreads();
    for (int o = 128; o > 0; o >>= 1) { if (t < o) sh[t] += sh[t + o]; __syncthreads(); }
    float mean = sh[0] * (1.f / 256.f);
    __syncthreads();
    float dv = v - mean;
    sh[t] = dv * dv;
    __syncthreads();
    for (int o = 128; o > 0; o >>= 1) { if (t < o) sh[t] += sh[t + o]; __syncthreads(); }
    float var = sh[0] * (1.f / 256.f);
    g_s[(size_t)row * 256 + t] += dv * rsqrtf(var + EPSV) * w[t] + bi[t];
}

// ---------------- head ----------------
__global__ void head_kernel(const float* __restrict__ nw, const float* __restrict__ nb) {
    int b = blockIdx.x, t = threadIdx.x;
    float acc = 0.f;
    for (int l = 0; l < 1024; l++) acc += g_s[(size_t)((b << 10) + l) * 256 + t];
    float m = acc * (1.f / 1024.f);
    __shared__ float sh[256];
    sh[t] = m;
    __syncthreads();
    for (int o = 128; o > 0; o >>= 1) { if (t < o) sh[t] += sh[t + o]; __syncthreads(); }
    float mu = sh[0] * (1.f / 256.f);
    __syncthreads();
    float dv = m - mu;
    sh[t] = dv * dv;
    __syncthreads();
    for (int o = 128; o > 0; o >>= 1) { if (t < o) sh[t] += sh[t + o]; __syncthreads(); }
    float var = sh[0] * (1.f / 256.f);
    g_v[b * 256 + t] = dv * rsqrtf(var + EPSV) * nw[t] + nb[t];
}

__global__ void fc_kernel(const float* __restrict__ fcw, const float* __restrict__ fcb,
                          float* __restrict__ out) {
    int idx = blockIdx.x * 256 + threadIdx.x;
    if (idx >= 4000) return;
    int b = idx / 1000, n = idx % 1000;
    float acc = fcb[n];
    const float* v = g_v + b * 256;
    const float* w = fcw + n * 256;
#pragma unroll 8
    for (int k = 0; k < 256; k++) acc += v[k] * w[k];
    out[idx] = acc;
}

__global__ void softmax_kernel(float* __restrict__ out) {
    int b = blockIdx.x, t = threadIdx.x;
    __shared__ float sh[256];
    const float* lg = out + b * 1000;
    float mx = -1e30f;
    for (int i = t; i < 1000; i += 256) mx = fmaxf(mx, lg[i]);
    sh[t] = mx;
    __syncthreads();
    for (int o = 128; o > 0; o >>= 1) { if (t < o) sh[t] = fmaxf(sh[t], sh[t + o]); __syncthreads(); }
    mx = sh[0];
    __syncthreads();
    float s = 0.f;
    for (int i = t; i < 1000; i += 256) s += expf(lg[i] - mx);
    sh[t] = s;
    __syncthreads();
    for (int o = 128; o > 0; o >>= 1) { if (t < o) sh[t] += sh[t + o]; __syncthreads(); }
    float inv = 1.f / sh[0];
    for (int i = t; i < 1000; i += 256) out[4000 + b * 1000 + i] = expf(lg[i] - mx) * inv;
}

// ---------------- launch ----------------
extern "C" void kernel_launch(void* const* d_in, const int* in_sizes, int n_in,
                              void* d_out, int out_size) {
    const float* x    = (const float*)d_in[0];
    const float* c1w  = (const float*)d_in[1];
    const float* c1b  = (const float*)d_in[2];
    const float* g1   = (const float*)d_in[3];
    const float* b1   = (const float*)d_in[4];
    const float* c2w  = (const float*)d_in[5];
    const float* c2b  = (const float*)d_in[6];
    const float* g2   = (const float*)d_in[7];
    const float* b2   = (const float*)d_in[8];
    const float* pw   = (const float*)d_in[9];
    const float* pb   = (const float*)d_in[10];
    const float* g3   = (const float*)d_in[11];
    const float* b3   = (const float*)d_in[12];
    const float* ipw  = (const float*)d_in[13];
    const float* ipb  = (const float*)d_in[14];
    const float* cw   = (const float*)d_in[15];
    const float* cb   = (const float*)d_in[16];
    const float* xpw  = (const float*)d_in[17];
    const float* dpw  = (const float*)d_in[18];
    const float* dpb  = (const float*)d_in[19];
    const float* alog = (const float*)d_in[20];
    const float* dssm = (const float*)d_in[21];
    const float* opw  = (const float*)d_in[22];
    const float* opb  = (const float*)d_in[23];
    const float* lnw  = (const float*)d_in[24];
    const float* lnb  = (const float*)d_in[25];
    const float* nw   = (const float*)d_in[26];
    const float* nb   = (const float*)d_in[27];
    const float* fcw  = (const float*)d_in[28];
    const float* fcb  = (const float*)d_in[29];

    float *p_col, *p_h2, *p_s, *p_xr, *p_xl, *p_xdbl, *p_delta, *p_y, *p_tmp;
    cudaGetSymbolAddress((void**)&p_col, g_col);
    cudaGetSymbolAddress((void**)&p_h2, g_h2);
    cudaGetSymbolAddress((void**)&p_s, g_s);
    cudaGetSymbolAddress((void**)&p_xr, g_xr);
    cudaGetSymbolAddress((void**)&p_xl, g_xl);
    cudaGetSymbolAddress((void**)&p_xdbl, g_xdbl);
    cudaGetSymbolAddress((void**)&p_delta, g_delta);
    cudaGetSymbolAddress((void**)&p_y, g_y);
    cudaGetSymbolAddress((void**)&p_tmp, g_tmp);

    // ---- stem ----
    conv1_kernel<<<8192, 256>>>(x, c1w, c1b, g1, b1);
    im2col1_kernel<<<(16384 * 1152) / 256, 256>>>();
    sgemm_nt<2><<<dim3(2, 128), 256>>>(p_col, 1152, c2w, 1152, p_h2, 256,
                                       16384, 256, 1152, c2b, g2, b2);
    im2col2_kernel<<<(4096 * 1024) / 256, 256>>>();
    sgemm_nt<2><<<dim3(2, 32), 256>>>(p_col, 1024, pw, 1024, p_s, 256,
                                      4096, 256, 1024, pb, g3, b3);

    // ---- mamba layers ----
    for (int i = 0; i < 4; i++) {
        const float* ipw_l  = ipw + (size_t)i * 1024 * 256;
        const float* ipb_l  = ipb + (size_t)i * 1024;
        const float* cw_l   = cw + (size_t)i * 512 * 4;
        const float* cb_l   = cb + (size_t)i * 512;
        const float* xpw_l  = xpw + (size_t)i * 64 * 512;
        const float* dpw_l  = dpw + (size_t)i * 512 * 32;
        const float* dpb_l  = dpb + (size_t)i * 512;
        const float* alog_l = alog + (size_t)i * 512 * 16;
        const float* dssm_l = dssm + (size_t)i * 512;
        const float* opw_l  = opw + (size_t)i * 256 * 512;
        const float* opb_l  = opb + (size_t)i * 256;
        const float* lnw_l  = lnw + (size_t)i * 256;
        const float* lnb_l  = lnb + (size_t)i * 256;

        sgemm_nt<1><<<dim3(8, 32), 256>>>(p_s, 256, ipw_l, 256, p_xr, 1024,
                                          4096, 1024, 256, ipb_l, nullptr, nullptr);
        dwconv_kernel<<<8192, 256>>>(cw_l, cb_l);
        sgemm_nt<0><<<dim3(1, 32), 256>>>(p_xl, 512, xpw_l, 512, p_xdbl, 64,
                                          4096, 64, 512, nullptr, nullptr, nullptr);
        sgemm_nt<3><<<dim3(4, 32), 256>>>(p_xdbl, 64, dpw_l, 32, p_delta, 512,
                                          4096, 512, 32, dpb_l, nullptr, nullptr);
        scan_kernel<<<128, 256>>>(alog_l, dssm_l);
        sgemm_nt<1><<<dim3(2, 32), 256>>>(p_y, 512, opw_l, 512, p_tmp, 256,
                                          4096, 256, 512, opb_l, nullptr, nullptr);
        ln_add_kernel<<<4096, 256>>>(lnw_l, lnb_l);
    }

    // ---- head ----
    head_kernel<<<4, 256>>>(nw, nb);
    fc_kernel<<<16, 256>>>(fcw, fcb, (float*)d_out);
    if (out_size >= 8000) softmax_kernel<<<4, 256>>>((float*)d_out);
}

// round 2
// speedup vs baseline: 1.3333x; 1.3333x over previous
#include <cuda_runtime.h>
#include <math.h>

#define EPSV 1e-5f

// ---------------- scratch (static device globals; no allocs) ----------------
__device__ float g_h1[4 * 64 * 64 * 128];    // conv1 out, NHWC
__device__ float g_col[16384 * 1152];        // im2col scratch (reused)
__device__ float g_h2[16384 * 256];          // conv2 out, NHWC
__device__ float g_s[4096 * 256];            // sequence [b*l, dm]
__device__ float g_xr[4096 * 1024];          // in_proj out (xi | res)
__device__ float g_xl[4096 * 512];           // after depthwise conv
__device__ float g_xdbl[4096 * 64];          // x_proj out (dt|B|C)
__device__ float g_delta[4096 * 512];
__device__ float g_y[4096 * 512];            // scan out * silu(res)
__device__ float g_tmp[4096 * 256];          // out_proj out
__device__ float g_part[128 * 256];          // head partials
__device__ float g_v[4 * 256];               // pooled+LN features

__device__ __forceinline__ float gelu_f(float v) {
    return 0.5f * v * (1.f + erff(v * 0.70710678118654752440f));
}
__device__ __forceinline__ float softplus_f(float x) {
    return fmaxf(x, 0.f) + log1pf(expf(-fabsf(x)));
}

// ---------------- tiled double-buffered SGEMM: C[M,N] = A[M,K] * B[N,K]^T ---
// Requires: M%BM==0, N%BN==0, K%8==0, lda%4==0, ldb%4==0, TN%4==0, TM%4==0.
// EPI: 0=none, 1=+bias, 2=gelu((acc+bias)*g/sqrt(1+eps)+beta), 3=softplus(acc+bias)
template <int BM, int BN, int TM, int TN, int EPI>
__global__ void __launch_bounds__((BM / TM) * (BN / TN))
sgemm_nt(const float* __restrict__ A, int lda,
         const float* __restrict__ B, int ldb,
         float* __restrict__ C, int ldc,
         int K,
         const float* __restrict__ bias,
         const float* __restrict__ bn_g,
         const float* __restrict__ bn_b) {
    constexpr int BK = 8;
    constexpr int NT = (BM / TM) * (BN / TN);
    constexpr int AROWS = NT / 2;          // rows of A loaded per pass (2 thr/row)
    constexpr int NLA = BM / AROWS;        // A load passes
    constexpr int BROWS = NT / 2;
    constexpr int NLB = BN / BROWS;

    __shared__ float As[2][BK][BM];
    __shared__ float Bs[2][BK][BN];

    const int tid = threadIdx.x;
    const int rowBase = blockIdx.y * BM;
    const int colBase = blockIdx.x * BN;
    const int tx = tid % (BN / TN);
    const int ty = tid / (BN / TN);
    const int lRow = tid >> 1;
    const int lCol = (tid & 1) * 4;

    const float* Ab = A + (size_t)(rowBase + lRow) * lda + lCol;
    const float* Bb = B + (size_t)(colBase + lRow) * ldb + lCol;

    float acc[TM][TN];
#pragma unroll
    for (int i = 0; i < TM; i++)
#pragma unroll
        for (int j = 0; j < TN; j++) acc[i][j] = 0.f;

    // preload tile 0
    float4 pa[NLA], pb[NLB];
#pragma unroll
    for (int p = 0; p < NLA; p++)
        pa[p] = *(const float4*)(Ab + (size_t)p * AROWS * lda);
#pragma unroll
    for (int p = 0; p < NLB; p++)
        pb[p] = *(const float4*)(Bb + (size_t)p * BROWS * ldb);
#pragma unroll
    for (int p = 0; p < NLA; p++) {
        As[0][lCol + 0][lRow + p * AROWS] = pa[p].x;
        As[0][lCol + 1][lRow + p * AROWS] = pa[p].y;
        As[0][lCol + 2][lRow + p * AROWS] = pa[p].z;
        As[0][lCol + 3][lRow + p * AROWS] = pa[p].w;
    }
#pragma unroll
    for (int p = 0; p < NLB; p++) {
        Bs[0][lCol + 0][lRow + p * BROWS] = pb[p].x;
        Bs[0][lCol + 1][lRow + p * BROWS] = pb[p].y;
        Bs[0][lCol + 2][lRow + p * BROWS] = pb[p].z;
        Bs[0][lCol + 3][lRow + p * BROWS] = pb[p].w;
    }
    __syncthreads();

    int buf = 0;
    for (int k0 = 0; k0 < K; k0 += BK) {
        const bool more = (k0 + BK) < K;
        if (more) {
#pragma unroll
            for (int p = 0; p < NLA; p++)
                pa[p] = *(const float4*)(Ab + (size_t)p * AROWS * lda + k0 + BK);
#pragma unroll
            for (int p = 0; p < NLB; p++)
                pb[p] = *(const float4*)(Bb + (size_t)p * BROWS * ldb + k0 + BK);
        }
#pragma unroll
        for (int kk = 0; kk < BK; kk++) {
            float ar[TM], br[TN];
#pragma unroll
            for (int i = 0; i < TM; i += 4)
                *(float4*)&ar[i] = *(const float4*)&As[buf][kk][ty * TM + i];
#pragma unroll
            for (int j = 0; j < TN; j += 4)
                *(float4*)&br[j] = *(const float4*)&Bs[buf][kk][tx * TN + j];
#pragma unroll
            for (int i = 0; i < TM; i++)
#pragma unroll
                for (int j = 0; j < TN; j++) acc[i][j] = fmaf(ar[i], br[j], acc[i][j]);
        }
        if (more) {
#pragma unroll
            for (int p = 0; p < NLA; p++) {
                As[buf ^ 1][lCol + 0][lRow + p * AROWS] = pa[p].x;
                As[buf ^ 1][lCol + 1][lRow + p * AROWS] = pa[p].y;
                As[buf ^ 1][lCol + 2][lRow + p * AROWS] = pa[p].z;
                As[buf ^ 1][lCol + 3][lRow + p * AROWS] = pa[p].w;
            }
#pragma unroll
            for (int p = 0; p < NLB; p++) {
                Bs[buf ^ 1][lCol + 0][lRow + p * BROWS] = pb[p].x;
                Bs[buf ^ 1][lCol + 1][lRow + p * BROWS] = pb[p].y;
                Bs[buf ^ 1][lCol + 2][lRow + p * BROWS] = pb[p].z;
                Bs[buf ^ 1][lCol + 3][lRow + p * BROWS] = pb[p].w;
            }
            __syncthreads();
            buf ^= 1;
        }
    }

#pragma unroll
    for (int i = 0; i < TM; i++) {
        const int r = rowBase + ty * TM + i;
        float* crow = C + (size_t)r * ldc + colBase + tx * TN;
#pragma unroll
        for (int j4 = 0; j4 < TN; j4 += 4) {
            float vv[4];
#pragma unroll
            for (int j = 0; j < 4; j++) {
                const int c = colBase + tx * TN + j4 + j;
                float v = acc[i][j4 + j];
                if (EPI == 1) v += bias[c];
                else if (EPI == 2) {
                    v += bias[c];
                    v = v * (bn_g[c] * rsqrtf(1.f + EPSV)) + bn_b[c];
                    v = gelu_f(v);
                } else if (EPI == 3) {
                    v = softplus_f(v + bias[c]);
                }
                vv[j] = v;
            }
            *(float4*)&crow[j4] = make_float4(vv[0], vv[1], vv[2], vv[3]);
        }
    }
}

// ---------------- conv stem ----------------
__global__ void conv1_kernel(const float* __restrict__ x, const float* __restrict__ w,
                             const float* __restrict__ bias, const float* __restrict__ g,
                             const float* __restrict__ bb) {
    int idx = blockIdx.x * 256 + threadIdx.x;
    if (idx >= 4 * 64 * 64 * 128) return;
    int co = idx & 127;
    int xx = (idx >> 7) & 63;
    int yy = (idx >> 13) & 63;
    int b = idx >> 19;
    float acc = bias[co];
#pragma unroll
    for (int ci = 0; ci < 3; ci++)
#pragma unroll
        for (int ky = 0; ky < 3; ky++) {
            int iy = yy + ky - 1;
            if ((unsigned)iy >= 64u) continue;
#pragma unroll
            for (int kx = 0; kx < 3; kx++) {
                int ix = xx + kx - 1;
                if ((unsigned)ix >= 64u) continue;
                acc += x[((b * 3 + ci) * 64 + iy) * 64 + ix] * w[((co * 3 + ci) * 3 + ky) * 3 + kx];
            }
        }
    float v = acc * (g[co] * rsqrtf(1.f + EPSV)) + bb[co];
    g_h1[idx] = gelu_f(v);
}

__global__ void im2col1_kernel() {
    int idx = blockIdx.x * 256 + threadIdx.x;
    if (idx >= 16384 * 1152) return;
    int k = idx % 1152;
    int row = idx / 1152;
    int ci = k / 9, r = k % 9;
    int ky = r / 3, kx = r % 3;
    int xx = row & 63, yy = (row >> 6) & 63, b = row >> 12;
    int iy = yy + ky - 1, ix = xx + kx - 1;
    float v = 0.f;
    if ((unsigned)iy < 64u && (unsigned)ix < 64u)
        v = g_h1[(((b * 64 + iy) * 64 + ix) << 7) + ci];
    g_col[idx] = v;
}

__global__ void im2col2_kernel() {
    int idx = blockIdx.x * 256 + threadIdx.x;
    if (idx >= 4096 * 1024) return;
    int k = idx & 1023;
    int row = idx >> 10;
    int ci = k >> 2, r = k & 3, ky = r >> 1, kx = r & 1;
    int ox = row & 31, oy = (row >> 5) & 31, b = row >> 10;
    g_col[idx] = g_h2[(((b * 64 + 2 * oy + ky) * 64 + 2 * ox + kx) << 8) + ci];
}

// ---------------- mamba pieces ----------------
__global__ void dwconv_kernel(const float* __restrict__ cw, const float* __restrict__ cb) {
    int idx = blockIdx.x * 256 + threadIdx.x;
    if (idx >= 4096 * 512) return;
    int d = idx & 511;
    int row = idx >> 9;
    int l = row & 1023, b = row >> 10;
    float acc = cb[d];
#pragma unroll
    for (int k = 0; k < 4; k++) {
        int ll = l + k - 1;
        if ((unsigned)ll < 1024u)
            acc += g_xr[((size_t)(b * 1024 + ll) << 10) + d] * cw[d * 4 + k];
    }
    g_xl[idx] = acc;
}

// 16 lanes per (b,d) chain, one lane per state n. Fuses +u*D and *silu(res).
__global__ void scan_kernel(const float* __restrict__ alog_l, const float* __restrict__ dssm_l) {
    int gid = blockIdx.x * 256 + threadIdx.x;
    int n = gid & 15;
    int grp = gid >> 4;     // (b,d)
    int d = grp & 511;
    int b = grp >> 9;
    const float Adn = -__expf(alog_l[d * 16 + n]);
    const float Dd = dssm_l[d];
    const float* pDelta = g_delta + ((size_t)b << 19) + d;
    const float* pU     = g_xl    + ((size_t)b << 19) + d;
    const float* pRes   = g_xr    + ((size_t)b << 20) + 512 + d;
    const float* pB     = g_xdbl  + ((size_t)b << 16) + 32 + n;
    const float* pC     = g_xdbl  + ((size_t)b << 16) + 48 + n;
    float*       pY     = g_y     + ((size_t)b << 19) + d;
    float h = 0.f;
    for (int l = 0; l < 1024; l++) {
        float dl = pDelta[(size_t)l << 9];
        float u  = pU[(size_t)l << 9];
        float Bv = pB[l << 6];
        float Cv = pC[l << 6];
        float a = __expf(dl * Adn);
        h = fmaf(a, h, dl * Bv * u);
        float p = h * Cv;
        p += __shfl_xor_sync(0xFFFFFFFFu, p, 1);
        p += __shfl_xor_sync(0xFFFFFFFFu, p, 2);
        p += __shfl_xor_sync(0xFFFFFFFFu, p, 4);
        p += __shfl_xor_sync(0xFFFFFFFFu, p, 8);
        if (n == 0) {
            float rr = pRes[(size_t)l << 10];
            float sil = rr * __frcp_rn(1.f + __expf(-rr));
            pY[(size_t)l << 9] = (p + u * Dd) * sil;
        }
    }
}

__global__ void ln_add_kernel(const float* __restrict__ w, const float* __restrict__ bi) {
    int row = blockIdx.x;
    int t = threadIdx.x;
    __shared__ float sh[256];
    float v = g_tmp[(size_t)row * 256 + t];
    sh[t] = v;
    __syncthreads();
    for (int o = 128; o > 0; o >>= 1) { if (t < o) sh[t] += sh[t + o]; __syncthreads(); }
    float mean = sh[0] * (1.f / 256.f);
    __syncthreads();
    float dv = v - mean;
    sh[t] = dv * dv;
    __syncthreads();
    for (int o = 128; o > 0; o >>= 1) { if (t < o) sh[t] += sh[t + o]; __syncthreads(); }
    float var = sh[0] * (1.f / 256.f);
    g_s[(size_t)row * 256 + t] += dv * rsqrtf(var + EPSV) * w[t] + bi[t];
}

// ---------------- head ----------------
__global__ void head1_kernel() {
    int b = blockIdx.x >> 5, ch = blockIdx.x & 31, t = threadIdx.x;
    float acc = 0.f;
    const float* p = g_s + (size_t)((b << 10) + ch * 32) * 256 + t;
#pragma unroll 8
    for (int l = 0; l < 32; l++) acc += p[(size_t)l * 256];
    g_part[blockIdx.x * 256 + t] = acc;
}

__global__ void head2_kernel(const float* __restrict__ nw, const float* __restrict__ nb) {
    int b = blockIdx.x, t = threadIdx.x;
    float acc = 0.f;
#pragma unroll
    for (int c = 0; c < 32; c++) acc += g_part[((b << 5) + c) * 256 + t];
    float m = acc * (1.f / 1024.f);
    __shared__ float sh[256];
    sh[t] = m;
    __syncthreads();
    for (int o = 128; o > 0; o >>= 1) { if (t < o) sh[t] += sh[t + o]; __syncthreads(); }
    float mu = sh[0] * (1.f / 256.f);
    __syncthreads();
    float dv = m - mu;
    sh[t] = dv * dv;
    __syncthreads();
    for (int o = 128; o > 0; o >>= 1) { if (t < o) sh[t] += sh[t + o]; __syncthreads(); }
    float var = sh[0] * (1.f / 256.f);
    g_v[b * 256 + t] = dv * rsqrtf(var + EPSV) * nw[t] + nb[t];
}

__global__ void fc_kernel(const float* __restrict__ fcw, const float* __restrict__ fcb,
                          float* __restrict__ out) {
    int idx = blockIdx.x * 256 + threadIdx.x;
    if (idx >= 4000) return;
    int b = idx / 1000, n = idx % 1000;
    float acc = fcb[n];
    const float* v = g_v + b * 256;
    const float* w = fcw + n * 256;
#pragma unroll 8
    for (int k = 0; k < 256; k++) acc += v[k] * w[k];
    out[idx] = acc;
}

__global__ void softmax_kernel(float* __restrict__ out) {
    int b = blockIdx.x, t = threadIdx.x;
    __shared__ float sh[256];
    const float* lg = out + b * 1000;
    float mx = -1e30f;
    for (int i = t; i < 1000; i += 256) mx = fmaxf(mx, lg[i]);
    sh[t] = mx;
    __syncthreads();
    for (int o = 128; o > 0; o >>= 1) { if (t < o) sh[t] = fmaxf(sh[t], sh[t + o]); __syncthreads(); }
    mx = sh[0];
    __syncthreads();
    float s = 0.f;
    for (int i = t; i < 1000; i += 256) s += expf(lg[i] - mx);
    sh[t] = s;
    __syncthreads();
    for (int o = 128; o > 0; o >>= 1) { if (t < o) sh[t] += sh[t + o]; __syncthreads(); }
    float inv = 1.f / sh[0];
    for (int i = t; i < 1000; i += 256) out[4000 + b * 1000 + i] = expf(lg[i] - mx) * inv;
}

// ---------------- launch ----------------
extern "C" void kernel_launch(void* const* d_in, const int* in_sizes, int n_in,
                              void* d_out, int out_size) {
    const float* x    = (const float*)d_in[0];
    const float* c1w  = (const float*)d_in[1];
    const float* c1b  = (const float*)d_in[2];
    const float* g1   = (const float*)d_in[3];
    const float* b1   = (const float*)d_in[4];
    const float* c2w  = (const float*)d_in[5];
    const float* c2b  = (const float*)d_in[6];
    const float* g2   = (const float*)d_in[7];
    const float* b2   = (const float*)d_in[8];
    const float* pw   = (const float*)d_in[9];
    const float* pb   = (const float*)d_in[10];
    const float* g3   = (const float*)d_in[11];
    const float* b3   = (const float*)d_in[12];
    const float* ipw  = (const float*)d_in[13];
    const float* ipb  = (const float*)d_in[14];
    const float* cw   = (const float*)d_in[15];
    const float* cb   = (const float*)d_in[16];
    const float* xpw  = (const float*)d_in[17];
    const float* dpw  = (const float*)d_in[18];
    const float* dpb  = (const float*)d_in[19];
    const float* alog = (const float*)d_in[20];
    const float* dssm = (const float*)d_in[21];
    const float* opw  = (const float*)d_in[22];
    const float* opb  = (const float*)d_in[23];
    const float* lnw  = (const float*)d_in[24];
    const float* lnb  = (const float*)d_in[25];
    const float* nw   = (const float*)d_in[26];
    const float* nb   = (const float*)d_in[27];
    const float* fcw  = (const float*)d_in[28];
    const float* fcb  = (const float*)d_in[29];

    float *p_col, *p_h2, *p_s, *p_xr, *p_xl, *p_xdbl, *p_delta, *p_y, *p_tmp;
    cudaGetSymbolAddress((void**)&p_col, g_col);
    cudaGetSymbolAddress((void**)&p_h2, g_h2);
    cudaGetSymbolAddress((void**)&p_s, g_s);
    cudaGetSymbolAddress((void**)&p_xr, g_xr);
    cudaGetSymbolAddress((void**)&p_xl, g_xl);
    cudaGetSymbolAddress((void**)&p_xdbl, g_xdbl);
    cudaGetSymbolAddress((void**)&p_delta, g_delta);
    cudaGetSymbolAddress((void**)&p_y, g_y);
    cudaGetSymbolAddress((void**)&p_tmp, g_tmp);

    // ---- stem ----
    conv1_kernel<<<8192, 256>>>(x, c1w, c1b, g1, b1);
    im2col1_kernel<<<(16384 * 1152) / 256, 256>>>();
    // conv2: M=16384, N=256, K=1152
    sgemm_nt<128, 128, 8, 8, 2><<<dim3(2, 128), 256>>>(p_col, 1152, c2w, 1152, p_h2, 256,
                                                       1152, c2b, g2, b2);
    im2col2_kernel<<<(4096 * 1024) / 256, 256>>>();
    // patchify: M=4096, N=256, K=1024
    sgemm_nt<64, 128, 8, 8, 2><<<dim3(2, 64), 128>>>(p_col, 1024, pw, 1024, p_s, 256,
                                                     1024, pb, g3, b3);

    // ---- mamba layers ----
    for (int i = 0; i < 4; i++) {
        const float* ipw_l  = ipw + (size_t)i * 1024 * 256;
        const float* ipb_l  = ipb + (size_t)i * 1024;
        const float* cw_l   = cw + (size_t)i * 512 * 4;
        const float* cb_l   = cb + (size_t)i * 512;
        const float* xpw_l  = xpw + (size_t)i * 64 * 512;
        const float* dpw_l  = dpw + (size_t)i * 512 * 32;
        const float* dpb_l  = dpb + (size_t)i * 512;
        const float* alog_l = alog + (size_t)i * 512 * 16;
        const float* dssm_l = dssm + (size_t)i * 512;
        const float* opw_l  = opw + (size_t)i * 256 * 512;
        const float* opb_l  = opb + (size_t)i * 256;
        const float* lnw_l  = lnw + (size_t)i * 256;
        const float* lnb_l  = lnb + (size_t)i * 256;

        // in_proj: M=4096, N=1024, K=256
        sgemm_nt<128, 128, 8, 8, 1><<<dim3(8, 32), 256>>>(p_s, 256, ipw_l, 256, p_xr, 1024,
                                                          256, ipb_l, nullptr, nullptr);
        dwconv_kernel<<<8192, 256>>>(cw_l, cb_l);
        // x_proj: M=4096, N=64, K=512
        sgemm_nt<64, 64, 8, 4, 0><<<dim3(1, 64), 128>>>(p_xl, 512, xpw_l, 512, p_xdbl, 64,
                                                        512, nullptr, nullptr, nullptr);
        // dt_proj: M=4096, N=512, K=32 (A rows stride 64, first 32 cols)
        sgemm_nt<64, 128, 8, 8, 3><<<dim3(4, 64), 128>>>(p_xdbl, 64, dpw_l, 32, p_delta, 512,
                                                         32, dpb_l, nullptr, nullptr);
        scan_kernel<<<128, 256>>>(alog_l, dssm_l);
        // out_proj: M=4096, N=256, K=512
        sgemm_nt<64, 128, 8, 8, 1><<<dim3(2, 64), 128>>>(p_y, 512, opw_l, 512, p_tmp, 256,
                                                         512, opb_l, nullptr, nullptr);
        ln_add_kernel<<<4096, 256>>>(lnw_l, lnb_l);
    }

    // ---- head ----
    head1_kernel<<<128, 256>>>();
    head2_kernel<<<4, 256>>>(nw, nb);
    fc_kernel<<<16, 256>>>(fcw, fcb, (float*)d_out);
    if (out_size >= 8000) softmax_kernel<<<4, 256>>>((float*)d_out);
}

// round 3
// speedup vs baseline: 3.3509x; 2.5132x over previous
#include <cuda_runtime.h>
#include <math.h>

#define EPSV 1e-5f

// ---------------- scratch (static device globals; no allocs) ----------------
__device__ float g_h1[4 * 64 * 64 * 128];    // conv1 out, NHWC
__device__ float g_h2[16384 * 256];          // conv2 out, NHWC
__device__ float g_s[4096 * 256];            // sequence [b*l, dm]
__device__ float g_xr[4096 * 1024];          // in_proj out (xi | silu(res))
__device__ float g_xl[4096 * 512];           // after depthwise conv
__device__ float g_xdbl[4096 * 64];          // x_proj out (dt|B|C)
__device__ float g_delta[4096 * 512];
__device__ float g_yt[512 * 4096];           // scan out, TRANSPOSED [d][row]
__device__ float g_tmp[4096 * 256];          // out_proj out
__device__ float g_part[128 * 256];          // head partials
__device__ float g_v[4 * 256];               // pooled+LN features
__device__ float g_w2p[256 * 1152];          // permuted conv2 weights (tap-major)
__device__ float g_wpp[256 * 1024];          // permuted patchify weights (tap-major)

__device__ __forceinline__ float gelu_f(float v) {
    return 0.5f * v * (1.f + erff(v * 0.70710678118654752440f));
}
__device__ __forceinline__ float softplus_f(float x) {
    return fmaxf(x, 0.f) + log1pf(expf(-fabsf(x)));
}

// ---------------- weight permutes (tap-major K so A gathers are contiguous) --
__global__ void permute_w2(const float* __restrict__ c2w) {
    int idx = blockIdx.x * 256 + threadIdx.x;
    if (idx >= 256 * 1152) return;
    int co = idx / 1152, k = idx % 1152;
    int r = k >> 7, ci = k & 127;
    g_w2p[idx] = c2w[co * 1152 + ci * 9 + r];
}
__global__ void permute_wp(const float* __restrict__ pw) {
    int idx = blockIdx.x * 256 + threadIdx.x;
    if (idx >= 256 * 1024) return;
    int co = idx >> 10, k = idx & 1023;
    int r = k >> 8, ci = k & 255;
    g_wpp[idx] = pw[(co << 10) + ci * 4 + r];
}

// ---------------- A-tile gather: 0=plain, 1=conv3x3 on g_h1, 2=patchify g_h2 -
template <int AMODE>
__device__ __forceinline__ float4 loadA(const float* __restrict__ A, int lda,
                                        int gr, int gk) {
    if (AMODE == 0) {
        return *(const float4*)(A + (size_t)gr * lda + gk);
    } else if (AMODE == 1) {
        int b = gr >> 12, yy = (gr >> 6) & 63, xx = gr & 63;
        int r = gk >> 7, ci = gk & 127;
        int ky = r / 3, kx = r - ky * 3;
        int iy = yy + ky - 1, ix = xx + kx - 1;
        if ((unsigned)iy < 64u && (unsigned)ix < 64u)
            return *(const float4*)&g_h1[(((b * 64 + iy) * 64 + ix) << 7) + ci];
        return make_float4(0.f, 0.f, 0.f, 0.f);
    } else {
        int b = gr >> 10, oy = (gr >> 5) & 31, ox = gr & 31;
        int r = gk >> 8, ci = gk & 255;
        int ky = r >> 1, kx = r & 1;
        return *(const float4*)&g_h2[(((b * 64 + 2 * oy + ky) * 64 + 2 * ox + kx) << 8) + ci];
    }
}

// ---------------- tiled double-buffered SGEMM: C[M,N] = A[M,K] * B[N,K]^T ---
// EPI: 0=none, 1=+bias, 2=bn+gelu, 3=softplus(+bias), 4=+bias then silu for c>=512
template <int BM, int BN, int TM, int TN, int AMODE, int EPI>
__global__ void __launch_bounds__((BM / TM) * (BN / TN))
sgemm_nt(const float* __restrict__ A, int lda,
         const float* __restrict__ B, int ldb,
         float* __restrict__ C, int ldc,
         int K,
         const float* __restrict__ bias,
         const float* __restrict__ bn_g,
         const float* __restrict__ bn_b) {
    constexpr int BK = 8;
    constexpr int NT = (BM / TM) * (BN / TN);
    constexpr int AROWS = NT / 2;
    constexpr int NLA = BM / AROWS;
    constexpr int BROWS = NT / 2;
    constexpr int NLB = BN / BROWS;

    __shared__ float As[2][BK][BM];
    __shared__ float Bs[2][BK][BN];

    const int tid = threadIdx.x;
    const int rowBase = blockIdx.y * BM;
    const int colBase = blockIdx.x * BN;
    const int tx = tid % (BN / TN);
    const int ty = tid / (BN / TN);
    const int lRow = tid >> 1;
    const int lCol = (tid & 1) * 4;

    const float* Bb = B + (size_t)(colBase + lRow) * ldb + lCol;

    float acc[TM][TN];
#pragma unroll
    for (int i = 0; i < TM; i++)
#pragma unroll
        for (int j = 0; j < TN; j++) acc[i][j] = 0.f;

    float4 pa[NLA], pb[NLB];
#pragma unroll
    for (int p = 0; p < NLA; p++)
        pa[p] = loadA<AMODE>(A, lda, rowBase + lRow + p * AROWS, lCol);
#pragma unroll
    for (int p = 0; p < NLB; p++)
        pb[p] = *(const float4*)(Bb + (size_t)p * BROWS * ldb);
#pragma unroll
    for (int p = 0; p < NLA; p++) {
        As[0][lCol + 0][lRow + p * AROWS] = pa[p].x;
        As[0][lCol + 1][lRow + p * AROWS] = pa[p].y;
        As[0][lCol + 2][lRow + p * AROWS] = pa[p].z;
        As[0][lCol + 3][lRow + p * AROWS] = pa[p].w;
    }
#pragma unroll
    for (int p = 0; p < NLB; p++) {
        Bs[0][lCol + 0][lRow + p * BROWS] = pb[p].x;
        Bs[0][lCol + 1][lRow + p * BROWS] = pb[p].y;
        Bs[0][lCol + 2][lRow + p * BROWS] = pb[p].z;
        Bs[0][lCol + 3][lRow + p * BROWS] = pb[p].w;
    }
    __syncthreads();

    int buf = 0;
    for (int k0 = 0; k0 < K; k0 += BK) {
        const bool more = (k0 + BK) < K;
        if (more) {
#pragma unroll
            for (int p = 0; p < NLA; p++)
                pa[p] = loadA<AMODE>(A, lda, rowBase + lRow + p * AROWS, k0 + BK + lCol);
#pragma unroll
            for (int p = 0; p < NLB; p++)
                pb[p] = *(const float4*)(Bb + (size_t)p * BROWS * ldb + k0 + BK);
        }
#pragma unroll
        for (int kk = 0; kk < BK; kk++) {
            float ar[TM], br[TN];
#pragma unroll
            for (int i = 0; i < TM; i += 4)
                *(float4*)&ar[i] = *(const float4*)&As[buf][kk][ty * TM + i];
#pragma unroll
            for (int j = 0; j < TN; j += 4)
                *(float4*)&br[j] = *(const float4*)&Bs[buf][kk][tx * TN + j];
#pragma unroll
            for (int i = 0; i < TM; i++)
#pragma unroll
                for (int j = 0; j < TN; j++) acc[i][j] = fmaf(ar[i], br[j], acc[i][j]);
        }
        if (more) {
#pragma unroll
            for (int p = 0; p < NLA; p++) {
                As[buf ^ 1][lCol + 0][lRow + p * AROWS] = pa[p].x;
                As[buf ^ 1][lCol + 1][lRow + p * AROWS] = pa[p].y;
                As[buf ^ 1][lCol + 2][lRow + p * AROWS] = pa[p].z;
                As[buf ^ 1][lCol + 3][lRow + p * AROWS] = pa[p].w;
            }
#pragma unroll
            for (int p = 0; p < NLB; p++) {
                Bs[buf ^ 1][lCol + 0][lRow + p * BROWS] = pb[p].x;
                Bs[buf ^ 1][lCol + 1][lRow + p * BROWS] = pb[p].y;
                Bs[buf ^ 1][lCol + 2][lRow + p * BROWS] = pb[p].z;
                Bs[buf ^ 1][lCol + 3][lRow + p * BROWS] = pb[p].w;
            }
            __syncthreads();
            buf ^= 1;
        }
    }

#pragma unroll
    for (int i = 0; i < TM; i++) {
        const int r = rowBase + ty * TM + i;
        float* crow = C + (size_t)r * ldc + colBase + tx * TN;
#pragma unroll
        for (int j4 = 0; j4 < TN; j4 += 4) {
            float vv[4];
#pragma unroll
            for (int j = 0; j < 4; j++) {
                const int c = colBase + tx * TN + j4 + j;
                float v = acc[i][j4 + j];
                if (EPI == 1) v += bias[c];
                else if (EPI == 2) {
                    v += bias[c];
                    v = v * (bn_g[c] * rsqrtf(1.f + EPSV)) + bn_b[c];
                    v = gelu_f(v);
                } else if (EPI == 3) {
                    v = softplus_f(v + bias[c]);
                } else if (EPI == 4) {
                    v += bias[c];
                    if (c >= 512) v = v * __frcp_rn(1.f + __expf(-v));
                }
                vv[j] = v;
            }
            *(float4*)&crow[j4] = make_float4(vv[0], vv[1], vv[2], vv[3]);
        }
    }
}

// ---------------- TN SGEMM (A stored K-major): C[M,N] = At^T * B^T -----------
// At: [K][Mtot], B: [N][K]. BM=BN=64, TM=4, TN=8, 128 threads.
template <int EPI>
__global__ void __launch_bounds__(128)
sgemm_tn64(const float* __restrict__ At, int Mtot,
           const float* __restrict__ B, int ldb,
           float* __restrict__ C, int ldc, int K,
           const float* __restrict__ bias) {
    __shared__ float As[2][8][64];
    __shared__ float Bs[2][8][64];
    const int tid = threadIdx.x;
    const int rowBase = blockIdx.y * 64;
    const int colBase = blockIdx.x * 64;
    const int tx = tid & 7, ty = tid >> 3;
    const int akr = tid >> 4, amc = (tid & 15) * 4;
    const int lRow = tid >> 1, lCol = (tid & 1) * 4;

    const float* Abase = At + (size_t)akr * Mtot + rowBase + amc;
    const float* Bb = B + (size_t)(colBase + lRow) * ldb + lCol;

    float acc[4][8];
#pragma unroll
    for (int i = 0; i < 4; i++)
#pragma unroll
        for (int j = 0; j < 8; j++) acc[i][j] = 0.f;

    float4 pa = *(const float4*)Abase;
    float4 pb = *(const float4*)Bb;
    *(float4*)&As[0][akr][amc] = pa;
    Bs[0][lCol + 0][lRow] = pb.x;
    Bs[0][lCol + 1][lRow] = pb.y;
    Bs[0][lCol + 2][lRow] = pb.z;
    Bs[0][lCol + 3][lRow] = pb.w;
    __syncthreads();

    int buf = 0;
    for (int k0 = 0; k0 < K; k0 += 8) {
        const bool more = (k0 + 8) < K;
        if (more) {
            pa = *(const float4*)(Abase + (size_t)(k0 + 8) * Mtot);
            pb = *(const float4*)(Bb + k0 + 8);
        }
#pragma unroll
        for (int kk = 0; kk < 8; kk++) {
            float ar[4], br[8];
            *(float4*)&ar[0] = *(const float4*)&As[buf][kk][ty * 4];
            *(float4*)&br[0] = *(const float4*)&Bs[buf][kk][tx * 8];
            *(float4*)&br[4] = *(const float4*)&Bs[buf][kk][tx * 8 + 4];
#pragma unroll
            for (int i = 0; i < 4; i++)
#pragma unroll
                for (int j = 0; j < 8; j++) acc[i][j] = fmaf(ar[i], br[j], acc[i][j]);
        }
        if (more) {
            *(float4*)&As[buf ^ 1][akr][amc] = pa;
            Bs[buf ^ 1][lCol + 0][lRow] = pb.x;
            Bs[buf ^ 1][lCol + 1][lRow] = pb.y;
            Bs[buf ^ 1][lCol + 2][lRow] = pb.z;
            Bs[buf ^ 1][lCol + 3][lRow] = pb.w;
            __syncthreads();
            buf ^= 1;
        }
    }

#pragma unroll
    for (int i = 0; i < 4; i++) {
        const int r = rowBase + ty * 4 + i;
        float* crow = C + (size_t)r * ldc + colBase + tx * 8;
#pragma unroll
        for (int j4 = 0; j4 < 8; j4 += 4) {
            float vv[4];
#pragma unroll
            for (int j = 0; j < 4; j++) {
                const int c = colBase + tx * 8 + j4 + j;
                float v = acc[i][j4 + j];
                if (EPI == 1) v += bias[c];
                vv[j] = v;
            }
            *(float4*)&crow[j4] = make_float4(vv[0], vv[1], vv[2], vv[3]);
        }
    }
}

// ---------------- conv stem ----------------
__global__ void conv1_kernel(const float* __restrict__ x, const float* __restrict__ w,
                             const float* __restrict__ bias, const float* __restrict__ g,
                             const float* __restrict__ bb) {
    int idx = blockIdx.x * 256 + threadIdx.x;
    if (idx >= 4 * 64 * 64 * 128) return;
    int co = idx & 127;
    int xx = (idx >> 7) & 63;
    int yy = (idx >> 13) & 63;
    int b = idx >> 19;
    float acc = bias[co];
#pragma unroll
    for (int ci = 0; ci < 3; ci++)
#pragma unroll
        for (int ky = 0; ky < 3; ky++) {
            int iy = yy + ky - 1;
            if ((unsigned)iy >= 64u) continue;
#pragma unroll
            for (int kx = 0; kx < 3; kx++) {
                int ix = xx + kx - 1;
                if ((unsigned)ix >= 64u) continue;
                acc += x[((b * 3 + ci) * 64 + iy) * 64 + ix] * w[((co * 3 + ci) * 3 + ky) * 3 + kx];
            }
        }
    float v = acc * (g[co] * rsqrtf(1.f + EPSV)) + bb[co];
    g_h1[idx] = gelu_f(v);
}

// ---------------- mamba pieces ----------------
__global__ void dwconv_kernel(const float* __restrict__ cw, const float* __restrict__ cb) {
    int idx = blockIdx.x * 256 + threadIdx.x;
    if (idx >= 4096 * 128) return;
    int d4 = (idx & 127) * 4;
    int row = idx >> 7;
    int l = row & 1023, b = row >> 10;
    float4 w0 = *(const float4*)&cw[(d4 + 0) * 4];
    float4 w1 = *(const float4*)&cw[(d4 + 1) * 4];
    float4 w2 = *(const float4*)&cw[(d4 + 2) * 4];
    float4 w3 = *(const float4*)&cw[(d4 + 3) * 4];
    float4 acc = *(const float4*)&cb[d4];
#pragma unroll
    for (int k = 0; k < 4; k++) {
        int ll = l + k - 1;
        if ((unsigned)ll >= 1024u) continue;
        float4 xv = *(const float4*)&g_xr[((size_t)(b * 1024 + ll) << 10) + d4];
        float wk0 = (k == 0) ? w0.x : (k == 1) ? w0.y : (k == 2) ? w0.z : w0.w;
        float wk1 = (k == 0) ? w1.x : (k == 1) ? w1.y : (k == 2) ? w1.z : w1.w;
        float wk2 = (k == 0) ? w2.x : (k == 1) ? w2.y : (k == 2) ? w2.z : w2.w;
        float wk3 = (k == 0) ? w3.x : (k == 1) ? w3.y : (k == 2) ? w3.z : w3.w;
        acc.x = fmaf(xv.x, wk0, acc.x);
        acc.y = fmaf(xv.y, wk1, acc.y);
        acc.z = fmaf(xv.z, wk2, acc.z);
        acc.w = fmaf(xv.w, wk3, acc.w);
    }
    *(float4*)&g_xl[((size_t)row << 9) + d4] = acc;
}

// Chunked scan: 1 block per (b,d). 16 chunks x 64 steps. 256 thr = 16 chunks x 16 states.
__global__ void __launch_bounds__(256)
scan_kernel(const float* __restrict__ alog_l, const float* __restrict__ dssm_l) {
    const int d = blockIdx.x & 511;
    const int b = blockIdx.x >> 9;
    const int t = threadIdx.x;
    const int n = t & 15;
    const int c = t >> 4;

    __shared__ float sh_hend[16][16];
    __shared__ float sh_S[16];
    __shared__ float sh_y[1024];

    const float Adn = -__expf(alog_l[d * 16 + n]);
    const float Dd = dssm_l[d];

    const size_t rb = (size_t)(b * 1024 + c * 64);
    const float* pDelta = g_delta + (rb << 9) + d;
    const float* pU     = g_xl    + (rb << 9) + d;
    const float* pRes   = g_xr    + (rb << 10) + 512 + d;
    const float* pB     = g_xdbl  + (rb << 6) + 32 + n;
    const float* pC     = g_xdbl  + (rb << 6) + 48 + n;

    // pass 1: chunk-local end state + delta sum
    float h = 0.f, S = 0.f;
#pragma unroll 4
    for (int j = 0; j < 64; j++) {
        float dl = pDelta[(size_t)j << 9];
        float u  = pU[(size_t)j << 9];
        float Bv = pB[j << 6];
        float a = __expf(dl * Adn);
        h = fmaf(a, h, dl * Bv * u);
        S += dl;
    }
    sh_hend[c][n] = h;
    if (n == 0) sh_S[c] = S;
    __syncthreads();

    // carry-in: H0 = sum_{c'<c} hend[c'][n] * exp(Adn * sum_{c''=c'+1..c-1} S)
    float H0 = 0.f, Q = 0.f;
    for (int cp = c - 1; cp >= 0; cp--) {
        H0 = fmaf(sh_hend[cp][n], __expf(Adn * Q), H0);
        Q += sh_S[cp];
    }

    // pass 2: apply with carry, reduce over n, stage y in smem
    h = H0;
#pragma unroll 2
    for (int j = 0; j < 64; j++) {
        float dl = pDelta[(size_t)j << 9];
        float u  = pU[(size_t)j << 9];
        float Bv = pB[j << 6];
        float Cv = pC[j << 6];
        float a = __expf(dl * Adn);
        h = fmaf(a, h, dl * Bv * u);
        float p = h * Cv;
        p += __shfl_xor_sync(0xFFFFFFFFu, p, 1);
        p += __shfl_xor_sync(0xFFFFFFFFu, p, 2);
        p += __shfl_xor_sync(0xFFFFFFFFu, p, 4);
        p += __shfl_xor_sync(0xFFFFFFFFu, p, 8);
        if (n == 0) {
            float sres = pRes[(size_t)j << 10];     // already silu'd by in_proj epilogue
            sh_y[c * 64 + j] = (p + u * Dd) * sres;
        }
    }
    __syncthreads();

    // coalesced transposed write: g_yt[d][b*1024 + l]
    *(float4*)&g_yt[(size_t)d * 4096 + (size_t)b * 1024 + t * 4] = *(float4*)&sh_y[t * 4];
}

__global__ void ln_add_kernel(const float* __restrict__ w, const float* __restrict__ bi) {
    int row = blockIdx.x;
    int t = threadIdx.x;
    __shared__ float sh[256];
    float v = g_tmp[(size_t)row * 256 + t];
    sh[t] = v;
    __syncthreads();
    for (int o = 128; o > 0; o >>= 1) { if (t < o) sh[t] += sh[t + o]; __syncthreads(); }
    float mean = sh[0] * (1.f / 256.f);
    __syncthreads();
    float dv = v - mean;
    sh[t] = dv * dv;
    __syncthreads();
    for (int o = 128; o > 0; o >>= 1) { if (t < o) sh[t] += sh[t + o]; __syncthreads(); }
    float var = sh[0] * (1.f / 256.f);
    g_s[(size_t)row * 256 + t] += dv * rsqrtf(var + EPSV) * w[t] + bi[t];
}

// ---------------- head ----------------
__global__ void head1_kernel() {
    int b = blockIdx.x >> 5, ch = blockIdx.x & 31, t = threadIdx.x;
    float acc = 0.f;
    const float* p = g_s + (size_t)((b << 10) + ch * 32) * 256 + t;
#pragma unroll 8
    for (int l = 0; l < 32; l++) acc += p[(size_t)l * 256];
    g_part[blockIdx.x * 256 + t] = acc;
}

__global__ void head2_kernel(const float* __restrict__ nw, const float* __restrict__ nb) {
    int b = blockIdx.x, t = threadIdx.x;
    float acc = 0.f;
#pragma unroll
    for (int c = 0; c < 32; c++) acc += g_part[((b << 5) + c) * 256 + t];
    float m = acc * (1.f / 1024.f);
    __shared__ float sh[256];
    sh[t] = m;
    __syncthreads();
    for (int o = 128; o > 0; o >>= 1) { if (t < o) sh[t] += sh[t + o]; __syncthreads(); }
    float mu = sh[0] * (1.f / 256.f);
    __syncthreads();
    float dv = m - mu;
    sh[t] = dv * dv;
    __syncthreads();
    for (int o = 128; o > 0; o >>= 1) { if (t < o) sh[t] += sh[t + o]; __syncthreads(); }
    float var = sh[0] * (1.f / 256.f);
    g_v[b * 256 + t] = dv * rsqrtf(var + EPSV) * nw[t] + nb[t];
}

__global__ void fc_kernel(const float* __restrict__ fcw, const float* __restrict__ fcb,
                          float* __restrict__ out) {
    int idx = blockIdx.x * 256 + threadIdx.x;
    if (idx >= 4000) return;
    int b = idx / 1000, n = idx % 1000;
    float acc = fcb[n];
    const float* v = g_v + b * 256;
    const float* w = fcw + n * 256;
#pragma unroll 8
    for (int k = 0; k < 256; k++) acc += v[k] * w[k];
    out[idx] = acc;
}

__global__ void softmax_kernel(float* __restrict__ out) {
    int b = blockIdx.x, t = threadIdx.x;
    __shared__ float sh[256];
    const float* lg = out + b * 1000;
    float mx = -1e30f;
    for (int i = t; i < 1000; i += 256) mx = fmaxf(mx, lg[i]);
    sh[t] = mx;
    __syncthreads();
    for (int o = 128; o > 0; o >>= 1) { if (t < o) sh[t] = fmaxf(sh[t], sh[t + o]); __syncthreads(); }
    mx = sh[0];
    __syncthreads();
    float s = 0.f;
    for (int i = t; i < 1000; i += 256) s += expf(lg[i] - mx);
    sh[t] = s;
    __syncthreads();
    for (int o = 128; o > 0; o >>= 1) { if (t < o) sh[t] += sh[t + o]; __syncthreads(); }
    float inv = 1.f / sh[0];
    for (int i = t; i < 1000; i += 256) out[4000 + b * 1000 + i] = expf(lg[i] - mx) * inv;
}

// ---------------- launch ----------------
extern "C" void kernel_launch(void* const* d_in, const int* in_sizes, int n_in,
                              void* d_out, int out_size) {
    const float* x    = (const float*)d_in[0];
    const float* c1w  = (const float*)d_in[1];
    const float* c1b  = (const float*)d_in[2];
    const float* g1   = (const float*)d_in[3];
    const float* b1   = (const float*)d_in[4];
    const float* c2w  = (const float*)d_in[5];
    const float* c2b  = (const float*)d_in[6];
    const float* g2   = (const float*)d_in[7];
    const float* b2   = (const float*)d_in[8];
    const float* pw   = (const float*)d_in[9];
    const float* pb   = (const float*)d_in[10];
    const float* g3   = (const float*)d_in[11];
    const float* b3   = (const float*)d_in[12];
    const float* ipw  = (const float*)d_in[13];
    const float* ipb  = (const float*)d_in[14];
    const float* cw   = (const float*)d_in[15];
    const float* cb   = (const float*)d_in[16];
    const float* xpw  = (const float*)d_in[17];
    const float* dpw  = (const float*)d_in[18];
    const float* dpb  = (const float*)d_in[19];
    const float* alog = (const float*)d_in[20];
    const float* dssm = (const float*)d_in[21];
    const float* opw  = (const float*)d_in[22];
    const float* opb  = (const float*)d_in[23];
    const float* lnw  = (const float*)d_in[24];
    const float* lnb  = (const float*)d_in[25];
    const float* nw   = (const float*)d_in[26];
    const float* nb   = (const float*)d_in[27];
    const float* fcw  = (const float*)d_in[28];
    const float* fcb  = (const float*)d_in[29];

    float *p_s, *p_xr, *p_xl, *p_xdbl, *p_delta, *p_yt, *p_tmp, *p_h2, *p_w2p, *p_wpp;
    cudaGetSymbolAddress((void**)&p_s, g_s);
    cudaGetSymbolAddress((void**)&p_xr, g_xr);
    cudaGetSymbolAddress((void**)&p_xl, g_xl);
    cudaGetSymbolAddress((void**)&p_xdbl, g_xdbl);
    cudaGetSymbolAddress((void**)&p_delta, g_delta);
    cudaGetSymbolAddress((void**)&p_yt, g_yt);
    cudaGetSymbolAddress((void**)&p_tmp, g_tmp);
    cudaGetSymbolAddress((void**)&p_h2, g_h2);
    cudaGetSymbolAddress((void**)&p_w2p, g_w2p);
    cudaGetSymbolAddress((void**)&p_wpp, g_wpp);

    // ---- stem ----
    permute_w2<<<(256 * 1152 + 255) / 256, 256>>>(c2w);
    permute_wp<<<(256 * 1024 + 255) / 256, 256>>>(pw);
    conv1_kernel<<<8192, 256>>>(x, c1w, c1b, g1, b1);
    // conv2 (implicit im2col): M=16384, N=256, K=1152
    sgemm_nt<128, 128, 8, 8, 1, 2><<<dim3(2, 128), 256>>>(nullptr, 0, p_w2p, 1152, p_h2, 256,
                                                          1152, c2b, g2, b2);
    // patchify (implicit): M=4096, N=256, K=1024
    sgemm_nt<64, 64, 4, 8, 2, 2><<<dim3(4, 64), 128>>>(nullptr, 0, p_wpp, 1024, p_s, 256,
                                                       1024, pb, g3, b3);

    // ---- mamba layers ----
    for (int i = 0; i < 4; i++) {
        const float* ipw_l  = ipw + (size_t)i * 1024 * 256;
        const float* ipb_l  = ipb + (size_t)i * 1024;
        const float* cw_l   = cw + (size_t)i * 512 * 4;
        const float* cb_l   = cb + (size_t)i * 512;
        const float* xpw_l  = xpw + (size_t)i * 64 * 512;
        const float* dpw_l  = dpw + (size_t)i * 512 * 32;
        const float* dpb_l  = dpb + (size_t)i * 512;
        const float* alog_l = alog + (size_t)i * 512 * 16;
        const float* dssm_l = dssm + (size_t)i * 512;
        const float* opw_l  = opw + (size_t)i * 256 * 512;
        const float* opb_l  = opb + (size_t)i * 256;
        const float* lnw_l  = lnw + (size_t)i * 256;
        const float* lnb_l  = lnb + (size_t)i * 256;

        // in_proj: M=4096, N=1024, K=256; silu applied to res half (cols>=512)
        sgemm_nt<128, 128, 8, 8, 0, 4><<<dim3(8, 32), 256>>>(p_s, 256, ipw_l, 256, p_xr, 1024,
                                                             256, ipb_l, nullptr, nullptr);
        dwconv_kernel<<<2048, 256>>>(cw_l, cb_l);
        // x_proj: M=4096, N=64, K=512
        sgemm_nt<64, 64, 4, 8, 0, 0><<<dim3(1, 64), 128>>>(p_xl, 512, xpw_l, 512, p_xdbl, 64,
                                                           512, nullptr, nullptr, nullptr);
        // dt_proj: M=4096, N=512, K=32
        sgemm_nt<64, 128, 8, 8, 0, 3><<<dim3(4, 64), 128>>>(p_xdbl, 64, dpw_l, 32, p_delta, 512,
                                                            32, dpb_l, nullptr, nullptr);
        scan_kernel<<<2048, 256>>>(alog_l, dssm_l);
        // out_proj (TN): At = g_yt [512][4096], B = opw [256][512]
        sgemm_tn64<1><<<dim3(4, 64), 128>>>(p_yt, 4096, opw_l, 512, p_tmp, 256,
                                            512, opb_l);
        ln_add_kernel<<<4096, 256>>>(lnw_l, lnb_l);
    }

    // ---- head ----
    head1_kernel<<<128, 256>>>();
    head2_kernel<<<4, 256>>>(nw, nb);
    fc_kernel<<<16, 256>>>(fcw, fcb, (float*)d_out);
    if (out_size >= 8000) softmax_kernel<<<4, 256>>>((float*)d_out);
}